// round 11
// baseline (speedup 1.0000x reference)
#include <cuda_runtime.h>

#define BS   8192
#define H    256
#define KH   128               // k per thread-half (split-K)
#define KC   64
#define RPB  64
#define NBLK (BS / RPB)        // 128 blocks, all co-resident (1 CTA/SM)
#define NTHR 512
#define SC   68                // cT row stride (16B-aligned, affine)
#define SZ   68                // zT row stride (16B-aligned, affine)

// Per-block column partials of normalized Q; epoch-based grid barrier counter
// (never reset -> safe across graph replays).
__device__ float g_colpart[NBLK * KC];
__device__ unsigned int g_bar = 0;

// ---------------------------------------------------------------------------
// Single persistent kernel, 512 threads, tile 64 rows x 64 cols per block.
// Main loop: split-K, per-thread 4x4 tile, 2x LDS.128 + 16 FFMA per k.
// ---------------------------------------------------------------------------
__global__ __launch_bounds__(NTHR, 1)
void cluster_kernel(const float* __restrict__ z, const float* __restrict__ cent,
                    float* __restrict__ Qout, float* __restrict__ Pout)
{
    extern __shared__ float smem[];
    float* cT     = smem;               // [256][SC]  cT[k][j]
    float* zT     = cT + H * SC;        // [256][SZ]  zT[k][r]
    float* xch    = zT + H * SZ;        // [256][17]  split-K accum exchange
    float* cnp    = xch + 256 * 17;     // [8][64]  (reused phase E)
    float* znp    = cnp + 8 * KC;       // [8][64]
    float* cn     = znp + 8 * KC;       // [64]  ||c_j||^2
    float* zz     = cn + KC;            // [64]  ||z_r||^2
    float* colred = zz + RPB;           // [16][64]
    float* csi_s  = colred + 16 * KC;   // [64]

    const int tid  = threadIdx.x;
    const int row0 = blockIdx.x * RPB;

    // ---------------- phase A: staging (coalesced LDG), fused norms --------
    {
        const int r  = tid >> 3;        // 0..63 (z-row / centroid index)
        const int cg = tid & 7;         // column group

        float zsq = 0.f;
        #pragma unroll
        for (int p = 0; p < 8; p++) {
            const int k0 = cg * 4 + p * 32;
            const float4 v = *(const float4*)(z + (size_t)(row0 + r) * H + k0);
            zT[(k0 + 0) * SZ + r] = v.x;
            zT[(k0 + 1) * SZ + r] = v.y;
            zT[(k0 + 2) * SZ + r] = v.z;
            zT[(k0 + 3) * SZ + r] = v.w;
            zsq = fmaf(v.x, v.x, zsq); zsq = fmaf(v.y, v.y, zsq);
            zsq = fmaf(v.z, v.z, zsq); zsq = fmaf(v.w, v.w, zsq);
        }
        znp[cg * 64 + r] = zsq;

        float csq = 0.f;
        #pragma unroll
        for (int p = 0; p < 8; p++) {
            const int k0 = cg * 4 + p * 32;
            const float4 v = *(const float4*)(cent + (size_t)r * H + k0);
            cT[(k0 + 0) * SC + r] = v.x;
            cT[(k0 + 1) * SC + r] = v.y;
            cT[(k0 + 2) * SC + r] = v.z;
            cT[(k0 + 3) * SC + r] = v.w;
            csq = fmaf(v.x, v.x, csq); csq = fmaf(v.y, v.y, csq);
            csq = fmaf(v.z, v.z, csq); csq = fmaf(v.w, v.w, csq);
        }
        cnp[cg * 64 + r] = csq;
    }
    __syncthreads();

    if (tid < 64) {
        float s = 0.f;
        #pragma unroll
        for (int g = 0; g < 8; g++) s += cnp[g * 64 + tid];
        cn[tid] = s;
    } else if (tid < 128) {
        const int r = tid - 64;
        float s = 0.f;
        #pragma unroll
        for (int g = 0; g < 8; g++) s += znp[g * 64 + r];
        zz[r] = s;
    }
    __syncthreads();

    // ---------------- phase B: split-K main loop, 4x4 tile per thread ------
    const int kh = tid >> 8;            // k-half: 0 or 1
    const int t  = tid & 255;
    const int tx = t & 15;              // cols 4*tx..4*tx+3
    const int ty = t >> 4;              // rows 4*ty..4*ty+3   (0..15)

    const float* cp = cT + (size_t)kh * KH * SC + 4 * tx;
    const float* zp = zT + (size_t)kh * KH * SZ + 4 * ty;

    float a[4][4];
    #pragma unroll
    for (int i = 0; i < 4; i++)
        #pragma unroll
        for (int j = 0; j < 4; j++) a[i][j] = 0.f;

    #pragma unroll 8
    for (int k = 0; k < KH; k++) {
        const float4 cv = *(const float4*)(cp + k * SC);
        const float4 zv = *(const float4*)(zp + k * SZ);
        a[0][0] = fmaf(zv.x, cv.x, a[0][0]); a[0][1] = fmaf(zv.x, cv.y, a[0][1]);
        a[0][2] = fmaf(zv.x, cv.z, a[0][2]); a[0][3] = fmaf(zv.x, cv.w, a[0][3]);
        a[1][0] = fmaf(zv.y, cv.x, a[1][0]); a[1][1] = fmaf(zv.y, cv.y, a[1][1]);
        a[1][2] = fmaf(zv.y, cv.z, a[1][2]); a[1][3] = fmaf(zv.y, cv.w, a[1][3]);
        a[2][0] = fmaf(zv.z, cv.x, a[2][0]); a[2][1] = fmaf(zv.z, cv.y, a[2][1]);
        a[2][2] = fmaf(zv.z, cv.z, a[2][2]); a[2][3] = fmaf(zv.z, cv.w, a[2][3]);
        a[3][0] = fmaf(zv.w, cv.x, a[3][0]); a[3][1] = fmaf(zv.w, cv.y, a[3][1]);
        a[3][2] = fmaf(zv.w, cv.z, a[3][2]); a[3][3] = fmaf(zv.w, cv.w, a[3][3]);
    }

    // split-K reduction: kh=1 stores, kh=0 accumulates (conflict-free stride 17)
    if (kh == 1) {
        #pragma unroll
        for (int i = 0; i < 4; i++)
            #pragma unroll
            for (int j = 0; j < 4; j++)
                xch[t * 17 + 4 * i + j] = a[i][j];
    }
    __syncthreads();

    if (kh == 0) {
        #pragma unroll
        for (int i = 0; i < 4; i++)
            #pragma unroll
            for (int j = 0; j < 4; j++)
                a[i][j] += xch[t * 17 + 4 * i + j];

        // ---------------- phase C: Q epilogue ------------------------------
        float cn4[4], zz4[4];
        #pragma unroll
        for (int j = 0; j < 4; j++) cn4[j] = cn[4 * tx + j];
        #pragma unroll
        for (int i = 0; i < 4; i++) zz4[i] = zz[4 * ty + i];

        #pragma unroll
        for (int i = 0; i < 4; i++)
            #pragma unroll
            for (int j = 0; j < 4; j++) {
                const float d2 = fmaxf(zz4[i] + cn4[j] - 2.f * a[i][j], 0.f);
                a[i][j] = 1.f / (1.f + sqrtf(d2));
            }

        float rs[4];
        #pragma unroll
        for (int i = 0; i < 4; i++)
            rs[i] = a[i][0] + a[i][1] + a[i][2] + a[i][3];
        #pragma unroll
        for (int m = 1; m < 16; m <<= 1) {
            #pragma unroll
            for (int i = 0; i < 4; i++)
                rs[i] += __shfl_xor_sync(0xffffffffu, rs[i], m);
        }
        #pragma unroll
        for (int i = 0; i < 4; i++) {
            const float inv = 1.f / rs[i];
            a[i][0] *= inv; a[i][1] *= inv; a[i][2] *= inv; a[i][3] *= inv;
        }

        // Q writes (coalesced: 16 tx lanes cover a 256B row)
        #pragma unroll
        for (int i = 0; i < 4; i++) {
            const int row = row0 + 4 * ty + i;
            *(float4*)(Qout + (size_t)row * KC + 4 * tx) =
                make_float4(a[i][0], a[i][1], a[i][2], a[i][3]);
        }

        // per-block column partials (deterministic smem tree)
        *(float4*)(colred + ty * KC + 4 * tx) =
            make_float4(a[0][0] + a[1][0] + a[2][0] + a[3][0],
                        a[0][1] + a[1][1] + a[2][1] + a[3][1],
                        a[0][2] + a[1][2] + a[2][2] + a[3][2],
                        a[0][3] + a[1][3] + a[2][3] + a[3][3]);
    }
    __syncthreads();
    {
        const int j = tid & 63, g = tid >> 6;      // g: 0..7
        if (g < 8)
            znp[g * 64 + j] = colred[g * KC + j] + colred[(g + 8) * KC + j];
    }
    __syncthreads();
    if (tid < KC) {
        float s = 0.f;
        #pragma unroll
        for (int g = 0; g < 8; g++) s += znp[g * 64 + tid];
        g_colpart[blockIdx.x * KC + tid] = s;
    }

    // ---------------- phase D: grid-wide barrier (epoch counter) -----------
    __threadfence();
    __syncthreads();
    if (tid == 0) {
        const unsigned int old    = atomicAdd(&g_bar, 1u);
        const unsigned int target = (old / NBLK + 1u) * (unsigned)NBLK;
        unsigned int cur;
        do {
            asm volatile("ld.acquire.gpu.global.u32 %0, [%1];"
                         : "=r"(cur) : "l"(&g_bar) : "memory");
            if (cur < target) __nanosleep(40);
        } while (cur < target);
    }
    __syncthreads();

    // ---------------- phase E: redundant csi reduce (L2 reads) -------------
    {
        const int j = tid & 63, pr = tid >> 6;     // pr: 0..7
        float s = 0.f;
        #pragma unroll 4
        for (int b = pr; b < NBLK; b += 8) s += __ldcg(&g_colpart[b * KC + j]);
        cnp[pr * 64 + j] = s;
    }
    __syncthreads();
    if (tid < KC) {
        float s = 0.f;
        #pragma unroll
        for (int g = 0; g < 8; g++) s += cnp[g * 64 + tid];
        csi_s[tid] = 1.0f / s;
    }
    __syncthreads();

    // ---------------- phase F: P from register-resident Q ------------------
    if (kh == 0) {
        const float w0 = csi_s[4 * tx + 0], w1 = csi_s[4 * tx + 1];
        const float w2 = csi_s[4 * tx + 2], w3 = csi_s[4 * tx + 3];

        float p[4][4], ps[4];
        #pragma unroll
        for (int i = 0; i < 4; i++) {
            p[i][0] = a[i][0] * a[i][0] * w0;
            p[i][1] = a[i][1] * a[i][1] * w1;
            p[i][2] = a[i][2] * a[i][2] * w2;
            p[i][3] = a[i][3] * a[i][3] * w3;
            ps[i] = p[i][0] + p[i][1] + p[i][2] + p[i][3];
        }
        #pragma unroll
        for (int m = 1; m < 16; m <<= 1) {
            #pragma unroll
            for (int i = 0; i < 4; i++)
                ps[i] += __shfl_xor_sync(0xffffffffu, ps[i], m);
        }
        #pragma unroll
        for (int i = 0; i < 4; i++) {
            const float inv = 1.f / ps[i];
            const int row = row0 + 4 * ty + i;
            *(float4*)(Pout + (size_t)row * KC + 4 * tx) =
                make_float4(p[i][0] * inv, p[i][1] * inv,
                            p[i][2] * inv, p[i][3] * inv);
        }
    }
}

// ---------------------------------------------------------------------------
extern "C" void kernel_launch(void* const* d_in, const int* in_sizes, int n_in,
                              void* d_out, int out_size)
{
    const float* z    = (const float*)d_in[0];   // (8192, 256)
    const float* cent = (const float*)d_in[1];   // (64, 256)
    float* Q = (float*)d_out;                    // (8192, 64)
    float* P = Q + (size_t)BS * KC;              // (8192, 64)

    const size_t smem_bytes =
        (size_t)(H * SC + H * SZ + 256 * 17 + 8 * KC + 8 * KC + KC + RPB
                 + 16 * KC + KC) * sizeof(float);   // ~166 KB -> 1 CTA/SM

    cudaFuncSetAttribute(cluster_kernel, cudaFuncAttributeMaxDynamicSharedMemorySize,
                         (int)smem_bytes);

    cluster_kernel<<<NBLK, NTHR, smem_bytes>>>(z, cent, Q, P);
}

// round 16
// speedup vs baseline: 1.4320x; 1.4320x over previous
#include <cuda_runtime.h>
#include <cstdint>

#define BS   8192
#define H    256
#define KC   64
#define MT   64                  // rows per CTA
#define NBLK (BS / MT)           // 128 CTAs, 1/SM, all co-resident
#define NTHR 512
#define SA   260                 // As/Cs row stride (floats): banks 4g+tg conflict-free
#define SQ   68                  // Qs row stride

__device__ float g_colpart[NBLK * KC];
__device__ unsigned int g_bar = 0;      // epoch barrier, never reset

__device__ __forceinline__ uint32_t f2tf(float x) {
    uint32_t r;
    asm("cvt.rna.tf32.f32 %0, %1;" : "=r"(r) : "f"(x));
    return r;
}

#define MMA_TF32(c, a0, a1, a2, a3, b0, b1)                                   \
    asm volatile(                                                              \
        "mma.sync.aligned.m16n8k8.row.col.f32.tf32.tf32.f32 "                 \
        "{%0,%1,%2,%3}, {%4,%5,%6,%7}, {%8,%9}, {%0,%1,%2,%3};"               \
        : "+f"((c)[0]), "+f"((c)[1]), "+f"((c)[2]), "+f"((c)[3])              \
        : "r"(a0), "r"(a1), "r"(a2), "r"(a3), "r"(b0), "r"(b1))

// ---------------------------------------------------------------------------
// 128 CTAs x 512 threads. Per CTA: 64 z-rows x 64 centroids, K=256.
// Warp grid 4x4: warp (wm,wn) -> rows 16wm..+15, cols 16wn..+15
// (two m16n8k8 tiles per k-step). A/B row-major in smem (stride SA),
// fragment loads are scalar LDS, conflict-free.
// ---------------------------------------------------------------------------
__global__ __launch_bounds__(NTHR, 1)
void cluster_kernel(const float* __restrict__ z, const float* __restrict__ cent,
                    float* __restrict__ Qout, float* __restrict__ Pout)
{
    extern __shared__ float smem[];
    uint32_t* As = (uint32_t*)smem;                 // [64][SA] tf32 z tile
    uint32_t* Cs = (uint32_t*)(smem + MT * SA);     // [64][SA] tf32 centroids
    float* zz   = smem + 2 * MT * SA;               // [64] ||z_r||^2 (fp32)
    float* cn   = zz + MT;                          // [64] ||c_j||^2 (fp32)
    float* rowp = cn + KC;                          // [64][4] row partials
    float* cred = rowp + MT * 4;                    // [8][64]
    float* csi  = cred + 8 * KC;                    // [64]
    float* Qs   = smem;                             // reuse As region: [64][SQ]

    const int tid = threadIdx.x;
    const int wid = tid >> 5, lid = tid & 31;
    const int row0 = blockIdx.x * MT;

    // ---------------- staging: raw row-major copies + fp32 norms -----------
    // warp w -> z rows 4w..4w+3 and centroid rows 4w..4w+3
    #pragma unroll
    for (int rr = 0; rr < 4; rr++) {
        const int r = wid * 4 + rr;
        const float4 v0 = *(const float4*)(z + (size_t)(row0 + r) * H + 4 * lid);
        const float4 v1 = *(const float4*)(z + (size_t)(row0 + r) * H + 128 + 4 * lid);
        *(uint4*)(As + r * SA + 4 * lid) =
            make_uint4(f2tf(v0.x), f2tf(v0.y), f2tf(v0.z), f2tf(v0.w));
        *(uint4*)(As + r * SA + 128 + 4 * lid) =
            make_uint4(f2tf(v1.x), f2tf(v1.y), f2tf(v1.z), f2tf(v1.w));
        float s = v0.x*v0.x + v0.y*v0.y + v0.z*v0.z + v0.w*v0.w
                + v1.x*v1.x + v1.y*v1.y + v1.z*v1.z + v1.w*v1.w;
        #pragma unroll
        for (int m = 1; m < 32; m <<= 1) s += __shfl_xor_sync(0xffffffffu, s, m);
        if (lid == 0) zz[r] = s;
    }
    #pragma unroll
    for (int rr = 0; rr < 4; rr++) {
        const int r = wid * 4 + rr;
        const float4 v0 = *(const float4*)(cent + (size_t)r * H + 4 * lid);
        const float4 v1 = *(const float4*)(cent + (size_t)r * H + 128 + 4 * lid);
        *(uint4*)(Cs + r * SA + 4 * lid) =
            make_uint4(f2tf(v0.x), f2tf(v0.y), f2tf(v0.z), f2tf(v0.w));
        *(uint4*)(Cs + r * SA + 128 + 4 * lid) =
            make_uint4(f2tf(v1.x), f2tf(v1.y), f2tf(v1.z), f2tf(v1.w));
        float s = v0.x*v0.x + v0.y*v0.y + v0.z*v0.z + v0.w*v0.w
                + v1.x*v1.x + v1.y*v1.y + v1.z*v1.z + v1.w*v1.w;
        #pragma unroll
        for (int m = 1; m < 32; m <<= 1) s += __shfl_xor_sync(0xffffffffu, s, m);
        if (lid == 0) cn[r] = s;
    }
    __syncthreads();

    // ---------------- tensor-core main loop --------------------------------
    const int wm = wid >> 2, wn = wid & 3;
    const int g  = lid >> 2, tg = lid & 3;

    float c0[4] = {0.f, 0.f, 0.f, 0.f};   // nt=0: cols 16wn+2tg{,+1}, rows g/g+8
    float c1[4] = {0.f, 0.f, 0.f, 0.f};   // nt=1: cols 16wn+8+2tg{,+1}

    const uint32_t* pa = As + (16 * wm + g) * SA + tg;
    const uint32_t* pb = Cs + (16 * wn + g) * SA + tg;

    #pragma unroll 4
    for (int s = 0; s < 32; s++) {
        const int k0 = 8 * s;
        const uint32_t a0 = pa[k0];
        const uint32_t a1 = pa[8 * SA + k0];
        const uint32_t a2 = pa[k0 + 4];
        const uint32_t a3 = pa[8 * SA + k0 + 4];
        const uint32_t b00 = pb[k0];
        const uint32_t b01 = pb[k0 + 4];
        const uint32_t b10 = pb[8 * SA + k0];
        const uint32_t b11 = pb[8 * SA + k0 + 4];
        MMA_TF32(c0, a0, a1, a2, a3, b00, b01);
        MMA_TF32(c1, a0, a1, a2, a3, b10, b11);
    }

    // ---------------- Q epilogue -------------------------------------------
    // element (nt, e, u): row = 16wm + 8e + g, col = 16wn + 8nt + 2tg + u,
    // value c{nt}[2e+u]
    const float zze0 = zz[16 * wm + g];
    const float zze1 = zz[16 * wm + 8 + g];
    const float cn00 = cn[16 * wn + 2 * tg],     cn01 = cn[16 * wn + 2 * tg + 1];
    const float cn10 = cn[16 * wn + 8 + 2 * tg], cn11 = cn[16 * wn + 8 + 2 * tg + 1];

    c0[0] = 1.f / (1.f + sqrtf(fmaxf(zze0 + cn00 - 2.f * c0[0], 0.f)));
    c0[1] = 1.f / (1.f + sqrtf(fmaxf(zze0 + cn01 - 2.f * c0[1], 0.f)));
    c0[2] = 1.f / (1.f + sqrtf(fmaxf(zze1 + cn00 - 2.f * c0[2], 0.f)));
    c0[3] = 1.f / (1.f + sqrtf(fmaxf(zze1 + cn01 - 2.f * c0[3], 0.f)));
    c1[0] = 1.f / (1.f + sqrtf(fmaxf(zze0 + cn10 - 2.f * c1[0], 0.f)));
    c1[1] = 1.f / (1.f + sqrtf(fmaxf(zze0 + cn11 - 2.f * c1[1], 0.f)));
    c1[2] = 1.f / (1.f + sqrtf(fmaxf(zze1 + cn10 - 2.f * c1[2], 0.f)));
    c1[3] = 1.f / (1.f + sqrtf(fmaxf(zze1 + cn11 - 2.f * c1[3], 0.f)));

    // 16-col row partials via 4-lane shuffle, then cross-warp via rowp smem
    float rp0 = c0[0] + c0[1] + c1[0] + c1[1];     // row e=0
    float rp1 = c0[2] + c0[3] + c1[2] + c1[3];     // row e=1
    rp0 += __shfl_xor_sync(0xffffffffu, rp0, 1);
    rp0 += __shfl_xor_sync(0xffffffffu, rp0, 2);
    rp1 += __shfl_xor_sync(0xffffffffu, rp1, 1);
    rp1 += __shfl_xor_sync(0xffffffffu, rp1, 2);
    if (tg == 0) {
        rowp[(16 * wm + g) * 4 + wn]     = rp0;
        rowp[(16 * wm + 8 + g) * 4 + wn] = rp1;
    }
    __syncthreads();
    {
        const float4 r4a = *(const float4*)(rowp + (16 * wm + g) * 4);
        const float4 r4b = *(const float4*)(rowp + (16 * wm + 8 + g) * 4);
        const float inv0 = 1.f / (r4a.x + r4a.y + r4a.z + r4a.w);
        const float inv1 = 1.f / (r4b.x + r4b.y + r4b.z + r4b.w);
        c0[0] *= inv0; c0[1] *= inv0; c1[0] *= inv0; c1[1] *= inv0;
        c0[2] *= inv1; c0[3] *= inv1; c1[2] *= inv1; c1[3] *= inv1;
    }

    // scatter normalized q into Qs (reuses As; all threads past MMA reads)
    {
        const int ra = 16 * wm + g, rb = ra + 8;
        const int cA = 16 * wn + 2 * tg, cB = cA + 8;
        *(float2*)(Qs + ra * SQ + cA) = make_float2(c0[0], c0[1]);
        *(float2*)(Qs + ra * SQ + cB) = make_float2(c1[0], c1[1]);
        *(float2*)(Qs + rb * SQ + cA) = make_float2(c0[2], c0[3]);
        *(float2*)(Qs + rb * SQ + cB) = make_float2(c1[2], c1[3]);
    }
    __syncthreads();

    // coalesced Q write (1024 float4 slots / 512 threads)
    #pragma unroll
    for (int i = tid; i < MT * 16; i += NTHR) {
        const int r = i >> 4, cc = (i & 15) * 4;
        const float4 v = *(const float4*)(Qs + r * SQ + cc);
        *(float4*)(Qout + (size_t)(row0 + r) * KC + cc) = v;
    }
    // per-block column partials (deterministic fixed order)
    if (tid < KC) {
        float s = 0.f;
        #pragma unroll 8
        for (int r = 0; r < MT; r++) s += Qs[r * SQ + tid];
        g_colpart[blockIdx.x * KC + tid] = s;
    }

    // ---------------- grid-wide epoch barrier (128 CTAs) -------------------
    __threadfence();
    __syncthreads();
    if (tid == 0) {
        const unsigned int old    = atomicAdd(&g_bar, 1u);
        const unsigned int target = (old / NBLK + 1u) * (unsigned)NBLK;
        unsigned int cur;
        do {
            asm volatile("ld.acquire.gpu.global.u32 %0, [%1];"
                         : "=r"(cur) : "l"(&g_bar) : "memory");
            if (cur < target) __nanosleep(40);
        } while (cur < target);
    }
    __syncthreads();

    // ---------------- redundant csi reduce ---------------------------------
    {
        const int j = tid & 63, pr = tid >> 6;          // pr 0..7
        float s = 0.f;
        #pragma unroll 4
        for (int b = pr; b < NBLK; b += 8) s += __ldcg(&g_colpart[b * KC + j]);
        cred[pr * KC + j] = s;
    }
    __syncthreads();
    if (tid < KC) {
        float s = 0.f;
        #pragma unroll
        for (int gidx = 0; gidx < 8; gidx++) s += cred[gidx * KC + tid];
        csi[tid] = 1.0f / s;
    }
    __syncthreads();

    // ---------------- P from register-resident q ---------------------------
    const float w00 = csi[16 * wn + 2 * tg],     w01 = csi[16 * wn + 2 * tg + 1];
    const float w10 = csi[16 * wn + 8 + 2 * tg], w11 = csi[16 * wn + 8 + 2 * tg + 1];

    c0[0] = c0[0] * c0[0] * w00; c0[1] = c0[1] * c0[1] * w01;
    c0[2] = c0[2] * c0[2] * w00; c0[3] = c0[3] * c0[3] * w01;
    c1[0] = c1[0] * c1[0] * w10; c1[1] = c1[1] * c1[1] * w11;
    c1[2] = c1[2] * c1[2] * w10; c1[3] = c1[3] * c1[3] * w11;

    float pp0 = c0[0] + c0[1] + c1[0] + c1[1];
    float pp1 = c0[2] + c0[3] + c1[2] + c1[3];
    pp0 += __shfl_xor_sync(0xffffffffu, pp0, 1);
    pp0 += __shfl_xor_sync(0xffffffffu, pp0, 2);
    pp1 += __shfl_xor_sync(0xffffffffu, pp1, 1);
    pp1 += __shfl_xor_sync(0xffffffffu, pp1, 2);
    if (tg == 0) {
        rowp[(16 * wm + g) * 4 + wn]     = pp0;
        rowp[(16 * wm + 8 + g) * 4 + wn] = pp1;
    }
    __syncthreads();
    {
        const float4 r4a = *(const float4*)(rowp + (16 * wm + g) * 4);
        const float4 r4b = *(const float4*)(rowp + (16 * wm + 8 + g) * 4);
        const float inv0 = 1.f / (r4a.x + r4a.y + r4a.z + r4a.w);
        const float inv1 = 1.f / (r4b.x + r4b.y + r4b.z + r4b.w);
        const int ra = 16 * wm + g, rb = ra + 8;
        const int cA = 16 * wn + 2 * tg, cB = cA + 8;
        *(float2*)(Qs + ra * SQ + cA) = make_float2(c0[0] * inv0, c0[1] * inv0);
        *(float2*)(Qs + ra * SQ + cB) = make_float2(c1[0] * inv0, c1[1] * inv0);
        *(float2*)(Qs + rb * SQ + cA) = make_float2(c0[2] * inv1, c0[3] * inv1);
        *(float2*)(Qs + rb * SQ + cB) = make_float2(c1[2] * inv1, c1[3] * inv1);
    }
    __syncthreads();

    // coalesced P write
    #pragma unroll
    for (int i = tid; i < MT * 16; i += NTHR) {
        const int r = i >> 4, cc = (i & 15) * 4;
        const float4 v = *(const float4*)(Qs + r * SQ + cc);
        *(float4*)(Pout + (size_t)(row0 + r) * KC + cc) = v;
    }
}

// ---------------------------------------------------------------------------
extern "C" void kernel_launch(void* const* d_in, const int* in_sizes, int n_in,
                              void* d_out, int out_size)
{
    const float* z    = (const float*)d_in[0];   // (8192, 256)
    const float* cent = (const float*)d_in[1];   // (64, 256)
    float* Q = (float*)d_out;                    // (8192, 64)
    float* P = Q + (size_t)BS * KC;              // (8192, 64)

    const size_t smem_bytes =
        (size_t)(2 * MT * SA + MT + KC + MT * 4 + 8 * KC + KC) * sizeof(float);

    cudaFuncSetAttribute(cluster_kernel, cudaFuncAttributeMaxDynamicSharedMemorySize,
                         (int)smem_bytes);

    cluster_kernel<<<NBLK, NTHR, smem_bytes>>>(z, cent, Q, P);
}